// round 8
// baseline (speedup 1.0000x reference)
#include <cuda_runtime.h>
#include <cuda_bf16.h>
#include <cstdint>
#include <math.h>
#include <float.h>

#define KCODES 8192
#define DIM    256
#define NROWS  16384

#define Q_OFF     0
#define LOSS_OFF  4194304
#define PERP_OFF  4194305
#define IDX_OFF   4194306
#define EMB_OFF   4210690

#define DECAYF 0.99f
#define OMD    ((float)(1.0 - 0.99))
#define KEPS   ((float)(8192.0 * 1e-5))
#define MARGIN 0.3f

// main-kernel smem geometry
#define PB      560                    // padded row bytes (280 bf16) -> conflict-free ldmatrix
#define BUFSZ   (64 * PB)              // one 64-code B buffer = 35840 B
#define SOFF_B  71680                  // after A region (128 rows * 560)
#define SOFF_ESQ (SOFF_B + 3 * BUFSZ)  // 179200
#define SMEM_MAIN (SOFF_ESQ + 3 * 256) // 179968

// ---------------- device scratch ----------------
__device__ __align__(16) __nv_bfloat16 g_Abf[(size_t)NROWS * DIM];   // 8 MB
__device__ __align__(16) __nv_bfloat16 g_Bc[(size_t)KCODES * DIM];   // 4 MB (code-major)
__device__ __align__(16) float g_ET[(size_t)KCODES * DIM];           // 8 MB (code-major fp32)
__device__ float g_esq[KCODES];
__device__ float g_dw[DIM * KCODES];
__device__ float g_counts[KCODES];
__device__ float g_scale[KCODES];
__device__ float g_loss;

// ---------------- PTX helpers (baseline compute_103 only) ----------------
__device__ __forceinline__ uint32_t s2u(const void* p) {
    uint32_t a;
    asm("{ .reg .u64 t; cvta.to.shared.u64 t, %1; cvt.u32.u64 %0, t; }" : "=r"(a) : "l"(p));
    return a;
}
__device__ __forceinline__ void cpa16(uint32_t dst, const void* src) {
    asm volatile("cp.async.cg.shared.global [%0], [%1], 16;" :: "r"(dst), "l"(src) : "memory");
}
__device__ __forceinline__ void cpcommit() {
    asm volatile("cp.async.commit_group;" ::: "memory");
}
template <int N> __device__ __forceinline__ void cpwait() {
    asm volatile("cp.async.wait_group %0;" :: "n"(N) : "memory");
}
__device__ __forceinline__ void ldsm4(unsigned& r0, unsigned& r1, unsigned& r2, unsigned& r3,
                                      uint32_t a) {
    asm volatile("ldmatrix.sync.aligned.m8n8.x4.shared.b16 {%0,%1,%2,%3},[%4];"
                 : "=r"(r0), "=r"(r1), "=r"(r2), "=r"(r3) : "r"(a));
}
__device__ __forceinline__ void mma_bf16(float (&d)[4], const unsigned (&a)[4],
                                         const unsigned b0, const unsigned b1) {
    asm volatile("mma.sync.aligned.m16n8k16.row.col.f32.bf16.bf16.f32 "
                 "{%0,%1,%2,%3},{%4,%5,%6,%7},{%8,%9},{%0,%1,%2,%3};"
                 : "+f"(d[0]), "+f"(d[1]), "+f"(d[2]), "+f"(d[3])
                 : "r"(a[0]), "r"(a[1]), "r"(a[2]), "r"(a[3]), "r"(b0), "r"(b1));
}
__device__ __forceinline__ void top4(float s, int k, float (&S)[4], int (&I)[4]) {
    if (s > S[3]) {
        if (s > S[1]) {
            if (s > S[0]) {
                S[3] = S[2]; I[3] = I[2]; S[2] = S[1]; I[2] = I[1];
                S[1] = S[0]; I[1] = I[0]; S[0] = s; I[0] = k;
            } else {
                S[3] = S[2]; I[3] = I[2]; S[2] = S[1]; I[2] = I[1];
                S[1] = s; I[1] = k;
            }
        } else {
            if (s > S[2]) { S[3] = S[2]; I[3] = I[2]; S[2] = s; I[2] = k; }
            else          { S[3] = s; I[3] = k; }
        }
    }
}

// ---------------- prepass kernels ----------------
__global__ void esq_kernel(const float* __restrict__ emb) {
    int k = blockIdx.x * 256 + threadIdx.x;
    float s = 0.f;
#pragma unroll 8
    for (int d = 0; d < DIM; ++d) {
        float v = __ldg(&emb[(size_t)d * KCODES + k]);
        s = fmaf(v, v, s);
    }
    g_esq[k] = s;
}

__global__ void prep_x(const float* __restrict__ x) {
    int i = blockIdx.x * 256 + threadIdx.x;              // float4 index
    float4 v = ((const float4*)x)[i];
    __nv_bfloat162 lo = __floats2bfloat162_rn(v.x, v.y);
    __nv_bfloat162 hi = __floats2bfloat162_rn(v.z, v.w);
    uint2 pk;
    pk.x = *(unsigned*)&lo; pk.y = *(unsigned*)&hi;
    ((uint2*)g_Abf)[i] = pk;
}

// transpose emb [D][K] -> ET fp32 [K][D] and Bc bf16 [K][D]
__global__ void prep_e(const float* __restrict__ emb) {
    __shared__ float tile[32][33];
    const int tx = threadIdx.x & 31, ty = threadIdx.x >> 5;    // ty 0..7
    const int k0 = blockIdx.x * 32, d0 = blockIdx.y * 32;
#pragma unroll
    for (int i = 0; i < 4; ++i)
        tile[ty + 8 * i][tx] = emb[(size_t)(d0 + ty + 8 * i) * KCODES + k0 + tx];
    __syncthreads();
#pragma unroll
    for (int i = 0; i < 4; ++i) {
        int kl = ty + 8 * i;
        float v = tile[tx][kl];
        size_t o = (size_t)(k0 + kl) * DIM + d0 + tx;
        g_ET[o] = v;
        g_Bc[o] = __float2bfloat16(v);
    }
}

// ---------------- main kernel ----------------
__device__ __forceinline__ void issueB(uint32_t sb, int t, int c, int buf) {
    const int r = t >> 3;                       // 512 threads: 8 threads per code row
    const int sub = t & 7;
    const char* src = (const char*)g_Bc + ((size_t)(c * 64 + r)) * 512 + sub * 64;
    uint32_t dst = sb + SOFF_B + buf * BUFSZ + r * PB + sub * 64;
#pragma unroll
    for (int i = 0; i < 4; ++i) cpa16(dst + i * 16, src + i * 16);
    if (t < 16)
        cpa16(sb + SOFF_ESQ + buf * 256 + t * 16, (const char*)g_esq + c * 256 + t * 16);
}

__global__ void __launch_bounds__(512, 1)
vq_hmma(const float* __restrict__ x, const float* __restrict__ emb,
        float* __restrict__ out) {
    extern __shared__ char sm[];
    const uint32_t sb = s2u(sm);
    const int t = threadIdx.x, l = t & 31, w = t >> 5;   // 16 warps
    const int g = w >> 1, h = w & 1;                     // row-group 0..7, code-half 0..1
    const int g0 = blockIdx.x * 128;

    // ---- stage A tile (128 rows) into smem via cp.async ----
    {
        const char* asrc = (const char*)g_Abf + (size_t)g0 * 512;
#pragma unroll
        for (int i = 0; i < 8; ++i) {
            int q = t + 512 * i, r = q >> 5, o = q & 31;
            cpa16(sb + r * PB + o * 16, asrc + (size_t)r * 512 + o * 16);
        }
        cpcommit();
    }
    // ---- B prologue: chunks 0..2 ----
#pragma unroll
    for (int p = 0; p < 3; ++p) { issueB(sb, t, p, p); cpcommit(); }

    cpwait<3>();                 // A resident
    __syncthreads();

    // ---- A fragments -> registers (held for whole kernel) ----
    unsigned aF[16][4];
    {
        uint32_t ab = sb + (g * 16 + (l & 15)) * PB + (l >> 4) * 16;
#pragma unroll
        for (int kt = 0; kt < 16; ++kt)
            ldsm4(aF[kt][0], aF[kt][1], aF[kt][2], aF[kt][3], ab + kt * 32);
    }

    float acc[4][4];
#pragma unroll
    for (int n = 0; n < 4; ++n)
#pragma unroll
        for (int j = 0; j < 4; ++j) acc[n][j] = 0.f;

    float Sa[4], Sb[4];
    int   Ia[4], Ib[4];
#pragma unroll
    for (int j = 0; j < 4; ++j) {
        Sa[j] = -FLT_MAX; Sb[j] = -FLT_MAX; Ia[j] = 0; Ib[j] = 0;
    }

    const uint32_t laneB = (uint32_t)(h * 32 + (l & 7) + ((l >> 4) << 3)) * PB
                         + ((l >> 3) & 1) * 16;
    const int q2 = (l & 3) * 2;

    // ---- stream 128 chunks of 64 codes (each warp: its 32-code half) ----
#pragma unroll 1
    for (int c = 0; c < 128; ++c) {
        const int buf = c % 3;
        cpwait<2>();
        __syncthreads();
        const uint32_t bb = sb + SOFF_B + buf * BUFSZ + laneB;
#pragma unroll
        for (int kt = 0; kt < 16; ++kt) {
            unsigned b[4][2];
#pragma unroll
            for (int p = 0; p < 2; ++p)
                ldsm4(b[2 * p][0], b[2 * p][1], b[2 * p + 1][0], b[2 * p + 1][1],
                      bb + p * (16 * PB) + kt * 32);
#pragma unroll
            for (int n = 0; n < 4; ++n)
                mma_bf16(acc[n], aF[kt], b[n][0], b[n][1]);
        }
        // per-chunk score epilogue (per-lane top-4 over this warp's 32 codes)
        const float* eSq = (const float*)(sm + SOFF_ESQ + buf * 256);
        const int cb = c * 64 + h * 32 + q2;
#pragma unroll
        for (int n = 0; n < 4; ++n) {
            float2 ev = *(const float2*)&eSq[h * 32 + n * 8 + q2];
            const int k0 = cb + n * 8;
            top4(fmaf(2.f, acc[n][0], -ev.x), k0,     Sa, Ia);
            top4(fmaf(2.f, acc[n][1], -ev.y), k0 + 1, Sa, Ia);
            top4(fmaf(2.f, acc[n][2], -ev.x), k0,     Sb, Ib);
            top4(fmaf(2.f, acc[n][3], -ev.y), k0 + 1, Sb, Ib);
            acc[n][0] = 0.f; acc[n][1] = 0.f; acc[n][2] = 0.f; acc[n][3] = 0.f;
        }
        __syncthreads();
        if (c + 3 < 128) issueB(sb, t, c + 3, buf);
        cpcommit();
    }
    cpwait<0>();

    // ---- dump candidates: 32 per row (2 warps x 4 lane-quads x top-4) ----
    int*   cand = (int*)sm;                 // 128*32 ints  = 16 KB
    float* sco  = (float*)(sm + 16384);     // 128*32 float = 16 KB
    int*   sIdx = (int*)(sm + 32768);       // 128 ints
    {
        const int rA = g * 16 + (l >> 2), rB = rA + 8;
        const int s0 = h * 16 + (l & 3) * 4;
#pragma unroll
        for (int j = 0; j < 4; ++j) {
            cand[rA * 32 + s0 + j] = Ia[j];
            sco [rA * 32 + s0 + j] = Sa[j];
            cand[rB * 32 + s0 + j] = Ib[j];
            sco [rB * 32 + s0 + j] = Sb[j];
        }
    }
    __syncthreads();

    // ---- selection: margin filter + exact sequential-d fp32 rescore ----
    if (t < 128) {
        float m = -FLT_MAX;
#pragma unroll
        for (int s = 0; s < 32; ++s) m = fmaxf(m, sco[t * 32 + s]);
        const float thr = m - MARGIN;
        const float4* xr = (const float4*)(x + (size_t)(g0 + t) * DIM);
        float bs = -FLT_MAX; int bk = 0x7fffffff;
#pragma unroll 1
        for (int s = 0; s < 32; ++s) {
            if (sco[t * 32 + s] < thr) continue;
            const int kc = cand[t * 32 + s];
            const float4* er = (const float4*)(g_ET + (size_t)kc * DIM);
            float dot = 0.f;                      // strictly sequential over d
#pragma unroll 8
            for (int ii = 0; ii < 64; ++ii) {
                float4 a = __ldg(&xr[ii]);
                float4 b = __ldg(&er[ii]);
                dot = fmaf(a.x, b.x, dot);
                dot = fmaf(a.y, b.y, dot);
                dot = fmaf(a.z, b.z, dot);
                dot = fmaf(a.w, b.w, dot);
            }
            float sc = fmaf(2.f, dot, -__ldg(&g_esq[kc]));
            if (sc > bs || (sc == bs && kc < bk)) { bs = sc; bk = kc; }
        }
        sIdx[t] = bk;
        out[IDX_OFF + g0 + t] = (float)bk;
        atomicAdd(&g_counts[bk], 1.0f);
    }
    __syncthreads();

    // ---- fused quantize / loss / dw (512 threads: d = t&255, row-half = t>>8) ----
    float lsum = 0.f;
    {
        const int d = t & 255, half = t >> 8;
        const float* xg = x + (size_t)(g0 + half * 64) * DIM + d;
        float* qg = out + (size_t)(g0 + half * 64) * DIM + d;
        const float* ecol = emb + (size_t)d * KCODES;
        float* dwcol = g_dw + (size_t)d * KCODES;
#pragma unroll 4
        for (int j = 0; j < 64; ++j) {
            const int bi = sIdx[half * 64 + j];
            float xv = xg[(size_t)j * DIM];
            float qv = __ldg(&ecol[bi]);
            float df = qv - xv;
            qg[(size_t)j * DIM] = xv + df;
            lsum += df * df;
            atomicAdd(&dwcol[bi], xv);
        }
    }
#pragma unroll
    for (int o = 16; o > 0; o >>= 1) lsum += __shfl_xor_sync(0xffffffffu, lsum, o);
    if (l == 0) atomicAdd(&g_loss, lsum);
}

// ---------------- finalize ----------------
__global__ void finalize_kernel(const float* __restrict__ ema_cs,
                                const int* __restrict__ counter,
                                float* __restrict__ out) {
    __shared__ float s_avg[KCODES];
    __shared__ float wn[8], wp[8], s_n;
    const int tid = threadIdx.x;
    const float debias = (float)(1.0 - pow(0.99, (double)(*counter + 1)));
    float nsum = 0.f, psum = 0.f;
    for (int i = tid; i < KCODES; i += 256) {
        float cnt = g_counts[i];
        float avg = (ema_cs[i] * DECAYF + cnt * OMD) / debias;
        s_avg[i] = avg; nsum += avg;
        float p = cnt * (1.0f / 16384.0f);
        psum += p * logf(p + 1e-10f);
    }
#pragma unroll
    for (int o = 16; o > 0; o >>= 1) {
        nsum += __shfl_xor_sync(0xffffffffu, nsum, o);
        psum += __shfl_xor_sync(0xffffffffu, psum, o);
    }
    if ((tid & 31) == 0) { wn[tid >> 5] = nsum; wp[tid >> 5] = psum; }
    __syncthreads();
    if (tid == 0) {
        float n = 0.f, ps = 0.f;
#pragma unroll
        for (int w = 0; w < 8; ++w) { n += wn[w]; ps += wp[w]; }
        s_n = n;
        out[LOSS_OFF] = 0.25f * (g_loss / 4194304.0f);
        out[PERP_OFF] = expf(-ps);
    }
    __syncthreads();
    const float n = s_n, denom = n + KEPS;
    for (int i = tid; i < KCODES; i += 256)
        g_scale[i] = 1.0f / (debias * (((s_avg[i] + 1e-5f) / denom) * n));
}

// ---------------- new_embeddings ----------------
__global__ void emb_out_kernel(const float* __restrict__ ema_dw,
                               const float* __restrict__ emb,
                               const int* __restrict__ istrain,
                               float* __restrict__ out_emb) {
    const int i = blockIdx.x * 256 + threadIdx.x;
    out_emb[i] = (*istrain)
        ? (ema_dw[i] * DECAYF + g_dw[i] * OMD) * g_scale[i & (KCODES - 1)]
        : emb[i];
}

// ---------------- host launch ----------------
extern "C" void kernel_launch(void* const* d_in, const int* in_sizes, int n_in,
                              void* d_out, int out_size) {
    const float* x       = (const float*)d_in[0];
    const float* emb     = (const float*)d_in[1];
    const float* ema_cs  = (const float*)d_in[2];
    const float* ema_dw  = (const float*)d_in[3];
    const int*   counter = (const int*)d_in[4];
    const int*   istrain = (const int*)d_in[5];
    float* out = (float*)d_out;

    void *p_dw, *p_cnt, *p_loss;
    cudaGetSymbolAddress(&p_dw, g_dw);
    cudaGetSymbolAddress(&p_cnt, g_counts);
    cudaGetSymbolAddress(&p_loss, g_loss);
    cudaMemsetAsync(p_dw, 0, sizeof(float) * DIM * KCODES, 0);
    cudaMemsetAsync(p_cnt, 0, sizeof(float) * KCODES, 0);
    cudaMemsetAsync(p_loss, 0, sizeof(float), 0);

    cudaFuncSetAttribute(vq_hmma, cudaFuncAttributeMaxDynamicSharedMemorySize, SMEM_MAIN);

    prep_x<<<(NROWS * DIM / 4) / 256, 256>>>(x);
    prep_e<<<dim3(KCODES / 32, DIM / 32), 256>>>(emb);
    esq_kernel<<<KCODES / 256, 256>>>(emb);
    vq_hmma<<<NROWS / 128, 512, SMEM_MAIN>>>(x, emb, out);
    finalize_kernel<<<1, 256>>>(ema_cs, counter, out);
    emb_out_kernel<<<(DIM * KCODES) / 256, 256>>>(ema_dw, emb, istrain, out + EMB_OFF);
}

// round 9
// speedup vs baseline: 1.0131x; 1.0131x over previous
#include <cuda_runtime.h>
#include <cuda_bf16.h>
#include <cstdint>
#include <math.h>
#include <float.h>

#define KCODES 8192
#define DIM    256
#define NROWS  16384

#define Q_OFF     0
#define LOSS_OFF  4194304
#define PERP_OFF  4194305
#define IDX_OFF   4194306
#define EMB_OFF   4210690

#define DECAYF 0.99f
#define OMD    ((float)(1.0 - 0.99))
#define KEPS   ((float)(8192.0 * 1e-5))
#define MARGIN 0.3f

// main-kernel smem geometry
#define PB      560                    // padded row bytes (280 bf16) -> conflict-free ldmatrix
#define BUFSZ   (64 * PB)              // one 64-code B buffer = 35840 B
#define SOFF_B  71680                  // after A region (128 rows * 560)
#define SOFF_ESQ (SOFF_B + 3 * BUFSZ)  // 179200
#define SMEM_MAIN (SOFF_ESQ + 3 * 256) // 179968

// ---------------- device scratch ----------------
__device__ __align__(16) __nv_bfloat16 g_Abf[(size_t)NROWS * DIM];   // 8 MB
__device__ __align__(16) __nv_bfloat16 g_Bc[(size_t)KCODES * DIM];   // 4 MB (code-major)
__device__ __align__(16) float g_ET[(size_t)KCODES * DIM];           // 8 MB (code-major fp32)
__device__ float g_esq[KCODES];
__device__ float g_dw[DIM * KCODES];
__device__ float g_counts[KCODES];
__device__ float g_scale[KCODES];
__device__ float g_loss;

// ---------------- PTX helpers (baseline compute_103 only) ----------------
__device__ __forceinline__ uint32_t s2u(const void* p) {
    uint32_t a;
    asm("{ .reg .u64 t; cvta.to.shared.u64 t, %1; cvt.u32.u64 %0, t; }" : "=r"(a) : "l"(p));
    return a;
}
__device__ __forceinline__ void cpa16(uint32_t dst, const void* src) {
    asm volatile("cp.async.cg.shared.global [%0], [%1], 16;" :: "r"(dst), "l"(src) : "memory");
}
__device__ __forceinline__ void cpcommit() {
    asm volatile("cp.async.commit_group;" ::: "memory");
}
template <int N> __device__ __forceinline__ void cpwait() {
    asm volatile("cp.async.wait_group %0;" :: "n"(N) : "memory");
}
__device__ __forceinline__ void ldsm4(unsigned& r0, unsigned& r1, unsigned& r2, unsigned& r3,
                                      uint32_t a) {
    asm volatile("ldmatrix.sync.aligned.m8n8.x4.shared.b16 {%0,%1,%2,%3},[%4];"
                 : "=r"(r0), "=r"(r1), "=r"(r2), "=r"(r3) : "r"(a));
}
__device__ __forceinline__ void mma_bf16(float (&d)[4], const unsigned (&a)[4],
                                         const unsigned b0, const unsigned b1) {
    asm volatile("mma.sync.aligned.m16n8k16.row.col.f32.bf16.bf16.f32 "
                 "{%0,%1,%2,%3},{%4,%5,%6,%7},{%8,%9},{%0,%1,%2,%3};"
                 : "+f"(d[0]), "+f"(d[1]), "+f"(d[2]), "+f"(d[3])
                 : "r"(a[0]), "r"(a[1]), "r"(a[2]), "r"(a[3]), "r"(b0), "r"(b1));
}
__device__ __forceinline__ void top4(float s, int k, float (&S)[4], int (&I)[4]) {
    if (s > S[3]) {
        if (s > S[1]) {
            if (s > S[0]) {
                S[3] = S[2]; I[3] = I[2]; S[2] = S[1]; I[2] = I[1];
                S[1] = S[0]; I[1] = I[0]; S[0] = s; I[0] = k;
            } else {
                S[3] = S[2]; I[3] = I[2]; S[2] = S[1]; I[2] = I[1];
                S[1] = s; I[1] = k;
            }
        } else {
            if (s > S[2]) { S[3] = S[2]; I[3] = I[2]; S[2] = s; I[2] = k; }
            else          { S[3] = s; I[3] = k; }
        }
    }
}

// ---------------- prepass kernels ----------------
__global__ void esq_kernel(const float* __restrict__ emb) {
    int k = blockIdx.x * 256 + threadIdx.x;
    float s = 0.f;
#pragma unroll 8
    for (int d = 0; d < DIM; ++d) {
        float v = __ldg(&emb[(size_t)d * KCODES + k]);
        s = fmaf(v, v, s);
    }
    g_esq[k] = s;
}

__global__ void prep_x(const float* __restrict__ x) {
    int i = blockIdx.x * 256 + threadIdx.x;              // float4 index
    float4 v = ((const float4*)x)[i];
    __nv_bfloat162 lo = __floats2bfloat162_rn(v.x, v.y);
    __nv_bfloat162 hi = __floats2bfloat162_rn(v.z, v.w);
    uint2 pk;
    pk.x = *(unsigned*)&lo; pk.y = *(unsigned*)&hi;
    ((uint2*)g_Abf)[i] = pk;
}

// transpose emb [D][K] -> ET fp32 [K][D] and Bc bf16 [K][D]
__global__ void prep_e(const float* __restrict__ emb) {
    __shared__ float tile[32][33];
    const int tx = threadIdx.x & 31, ty = threadIdx.x >> 5;    // ty 0..7
    const int k0 = blockIdx.x * 32, d0 = blockIdx.y * 32;
#pragma unroll
    for (int i = 0; i < 4; ++i)
        tile[ty + 8 * i][tx] = emb[(size_t)(d0 + ty + 8 * i) * KCODES + k0 + tx];
    __syncthreads();
#pragma unroll
    for (int i = 0; i < 4; ++i) {
        int kl = ty + 8 * i;
        float v = tile[tx][kl];
        size_t o = (size_t)(k0 + kl) * DIM + d0 + tx;
        g_ET[o] = v;
        g_Bc[o] = __float2bfloat16(v);
    }
}

// ---------------- main kernel ----------------
__device__ __forceinline__ void issueB(uint32_t sb, int t, int c, int buf) {
    const int r = t >> 2;
    const char* src = (const char*)g_Bc + ((size_t)(c * 64 + r)) * 512 + (t & 3) * 16;
    uint32_t dst = sb + SOFF_B + buf * BUFSZ + r * PB + (t & 3) * 16;
#pragma unroll
    for (int i = 0; i < 8; ++i) cpa16(dst + i * 64, src + i * 64);
    if (t < 16)
        cpa16(sb + SOFF_ESQ + buf * 256 + t * 16, (const char*)g_esq + c * 256 + t * 16);
}

__global__ void __launch_bounds__(256, 1)
vq_hmma(const float* __restrict__ x, const float* __restrict__ emb,
        float* __restrict__ out) {
    extern __shared__ char sm[];
    const uint32_t sb = s2u(sm);
    const int t = threadIdx.x, l = t & 31, w = t >> 5;   // 8 warps
    const int g = w >> 1, h = w & 1;                     // row-group 0..3 (32 rows), code-half
    const int g0 = blockIdx.x * 128;

    // ---- stage A tile (128 rows) into smem via cp.async ----
    {
        const char* asrc = (const char*)g_Abf + (size_t)g0 * 512;
#pragma unroll
        for (int i = 0; i < 16; ++i) {
            int q = t + 256 * i, r = q >> 5, o = q & 31;
            cpa16(sb + r * PB + o * 16, asrc + (size_t)r * 512 + o * 16);
        }
        cpcommit();
    }
    // ---- B prologue: chunks 0..2 ----
#pragma unroll
    for (int p = 0; p < 3; ++p) { issueB(sb, t, p, p); cpcommit(); }

    cpwait<3>();                 // A resident
    __syncthreads();

    // ---- A fragments -> registers: 32 rows per warp (2 m16 tiles) ----
    unsigned aF[2][16][4];
    {
        uint32_t ab = sb + (g * 32 + (l & 15)) * PB + (l >> 4) * 16;
#pragma unroll
        for (int m = 0; m < 2; ++m)
#pragma unroll
            for (int kt = 0; kt < 16; ++kt)
                ldsm4(aF[m][kt][0], aF[m][kt][1], aF[m][kt][2], aF[m][kt][3],
                      ab + m * (16 * PB) + kt * 32);
    }

    float acc[2][4][4];
#pragma unroll
    for (int m = 0; m < 2; ++m)
#pragma unroll
        for (int n = 0; n < 4; ++n)
#pragma unroll
            for (int j = 0; j < 4; ++j) acc[m][n][j] = 0.f;

    // 4 top-4 sets: [m*2 + (row-half within tile)]
    float S[4][4];
    int   I[4][4];
#pragma unroll
    for (int u = 0; u < 4; ++u)
#pragma unroll
        for (int j = 0; j < 4; ++j) { S[u][j] = -FLT_MAX; I[u][j] = 0; }

    const uint32_t laneB = (uint32_t)(h * 32 + (l & 7) + ((l >> 4) << 3)) * PB
                         + ((l >> 3) & 1) * 16;
    const int q2 = (l & 3) * 2;

    // ---- stream 128 chunks of 64 codes (each warp: its 32-code half, 32 rows) ----
#pragma unroll 1
    for (int c = 0; c < 128; ++c) {
        const int buf = c % 3;
        cpwait<2>();
        __syncthreads();
        const uint32_t bb = sb + SOFF_B + buf * BUFSZ + laneB;
#pragma unroll
        for (int kt = 0; kt < 16; ++kt) {
            unsigned b[4][2];
#pragma unroll
            for (int p = 0; p < 2; ++p)
                ldsm4(b[2 * p][0], b[2 * p][1], b[2 * p + 1][0], b[2 * p + 1][1],
                      bb + p * (16 * PB) + kt * 32);
#pragma unroll
            for (int m = 0; m < 2; ++m)
#pragma unroll
                for (int n = 0; n < 4; ++n)
                    mma_bf16(acc[m][n], aF[m][kt], b[n][0], b[n][1]);
        }
        // per-chunk score epilogue (per-lane top-4, 4 row-positions)
        const float* eSq = (const float*)(sm + SOFF_ESQ + buf * 256);
        const int cb = c * 64 + h * 32 + q2;
#pragma unroll
        for (int m = 0; m < 2; ++m) {
#pragma unroll
            for (int n = 0; n < 4; ++n) {
                float2 ev = *(const float2*)&eSq[h * 32 + n * 8 + q2];
                const int k0 = cb + n * 8;
                top4(fmaf(2.f, acc[m][n][0], -ev.x), k0,     S[m * 2],     I[m * 2]);
                top4(fmaf(2.f, acc[m][n][1], -ev.y), k0 + 1, S[m * 2],     I[m * 2]);
                top4(fmaf(2.f, acc[m][n][2], -ev.x), k0,     S[m * 2 + 1], I[m * 2 + 1]);
                top4(fmaf(2.f, acc[m][n][3], -ev.y), k0 + 1, S[m * 2 + 1], I[m * 2 + 1]);
                acc[m][n][0] = 0.f; acc[m][n][1] = 0.f;
                acc[m][n][2] = 0.f; acc[m][n][3] = 0.f;
            }
        }
        __syncthreads();
        if (c + 3 < 128) issueB(sb, t, c + 3, buf);
        cpcommit();
    }
    cpwait<0>();

    // ---- dump candidates: 32 per row (2 halves x 4 lane-quads x top-4) ----
    int*   cand = (int*)sm;                 // 128*32 ints  = 16 KB
    float* sco  = (float*)(sm + 16384);     // 128*32 float = 16 KB
    int*   sIdx = (int*)(sm + 32768);       // 128 ints
    {
        const int s0 = h * 16 + (l & 3) * 4;
#pragma unroll
        for (int m = 0; m < 2; ++m) {
            const int rA = g * 32 + m * 16 + (l >> 2), rB = rA + 8;
#pragma unroll
            for (int j = 0; j < 4; ++j) {
                cand[rA * 32 + s0 + j] = I[m * 2][j];
                sco [rA * 32 + s0 + j] = S[m * 2][j];
                cand[rB * 32 + s0 + j] = I[m * 2 + 1][j];
                sco [rB * 32 + s0 + j] = S[m * 2 + 1][j];
            }
        }
    }
    __syncthreads();

    // ---- selection: margin filter + exact sequential-d fp32 rescore ----
    if (t < 128) {
        float m = -FLT_MAX;
#pragma unroll
        for (int s = 0; s < 32; ++s) m = fmaxf(m, sco[t * 32 + s]);
        const float thr = m - MARGIN;
        const float4* xr = (const float4*)(x + (size_t)(g0 + t) * DIM);
        float bs = -FLT_MAX; int bk = 0x7fffffff;
#pragma unroll 1
        for (int s = 0; s < 32; ++s) {
            if (sco[t * 32 + s] < thr) continue;
            const int kc = cand[t * 32 + s];
            const float4* er = (const float4*)(g_ET + (size_t)kc * DIM);
            float dot = 0.f;                      // strictly sequential over d
#pragma unroll 8
            for (int ii = 0; ii < 64; ++ii) {
                float4 a = __ldg(&xr[ii]);
                float4 b = __ldg(&er[ii]);
                dot = fmaf(a.x, b.x, dot);
                dot = fmaf(a.y, b.y, dot);
                dot = fmaf(a.z, b.z, dot);
                dot = fmaf(a.w, b.w, dot);
            }
            float sc = fmaf(2.f, dot, -__ldg(&g_esq[kc]));
            if (sc > bs || (sc == bs && kc < bk)) { bs = sc; bk = kc; }
        }
        sIdx[t] = bk;
        out[IDX_OFF + g0 + t] = (float)bk;
        atomicAdd(&g_counts[bk], 1.0f);
    }
    __syncthreads();

    // ---- fused quantize / loss / dw (256 threads: d = t, 128 rows) ----
    float lsum = 0.f;
    {
        const float* xg = x + (size_t)g0 * DIM + t;
        float* qg = out + (size_t)g0 * DIM + t;
        const float* ecol = emb + (size_t)t * KCODES;
        float* dwcol = g_dw + (size_t)t * KCODES;
#pragma unroll 4
        for (int j = 0; j < 128; ++j) {
            const int bi = sIdx[j];
            float xv = xg[(size_t)j * DIM];
            float qv = __ldg(&ecol[bi]);
            float df = qv - xv;
            qg[(size_t)j * DIM] = xv + df;
            lsum += df * df;
            atomicAdd(&dwcol[bi], xv);
        }
    }
#pragma unroll
    for (int o = 16; o > 0; o >>= 1) lsum += __shfl_xor_sync(0xffffffffu, lsum, o);
    if (l == 0) atomicAdd(&g_loss, lsum);
}

// ---------------- finalize ----------------
__global__ void finalize_kernel(const float* __restrict__ ema_cs,
                                const int* __restrict__ counter,
                                float* __restrict__ out) {
    __shared__ float s_avg[KCODES];
    __shared__ float wn[8], wp[8], s_n;
    const int tid = threadIdx.x;
    const float debias = (float)(1.0 - pow(0.99, (double)(*counter + 1)));
    float nsum = 0.f, psum = 0.f;
    for (int i = tid; i < KCODES; i += 256) {
        float cnt = g_counts[i];
        float avg = (ema_cs[i] * DECAYF + cnt * OMD) / debias;
        s_avg[i] = avg; nsum += avg;
        float p = cnt * (1.0f / 16384.0f);
        psum += p * logf(p + 1e-10f);
    }
#pragma unroll
    for (int o = 16; o > 0; o >>= 1) {
        nsum += __shfl_xor_sync(0xffffffffu, nsum, o);
        psum += __shfl_xor_sync(0xffffffffu, psum, o);
    }
    if ((tid & 31) == 0) { wn[tid >> 5] = nsum; wp[tid >> 5] = psum; }
    __syncthreads();
    if (tid == 0) {
        float n = 0.f, ps = 0.f;
#pragma unroll
        for (int w = 0; w < 8; ++w) { n += wn[w]; ps += wp[w]; }
        s_n = n;
        out[LOSS_OFF] = 0.25f * (g_loss / 4194304.0f);
        out[PERP_OFF] = expf(-ps);
    }
    __syncthreads();
    const float n = s_n, denom = n + KEPS;
    for (int i = tid; i < KCODES; i += 256)
        g_scale[i] = 1.0f / (debias * (((s_avg[i] + 1e-5f) / denom) * n));
}

// ---------------- new_embeddings ----------------
__global__ void emb_out_kernel(const float* __restrict__ ema_dw,
                               const float* __restrict__ emb,
                               const int* __restrict__ istrain,
                               float* __restrict__ out_emb) {
    const int i = blockIdx.x * 256 + threadIdx.x;
    out_emb[i] = (*istrain)
        ? (ema_dw[i] * DECAYF + g_dw[i] * OMD) * g_scale[i & (KCODES - 1)]
        : emb[i];
}

// ---------------- host launch ----------------
extern "C" void kernel_launch(void* const* d_in, const int* in_sizes, int n_in,
                              void* d_out, int out_size) {
    const float* x       = (const float*)d_in[0];
    const float* emb     = (const float*)d_in[1];
    const float* ema_cs  = (const float*)d_in[2];
    const float* ema_dw  = (const float*)d_in[3];
    const int*   counter = (const int*)d_in[4];
    const int*   istrain = (const int*)d_in[5];
    float* out = (float*)d_out;

    void *p_dw, *p_cnt, *p_loss;
    cudaGetSymbolAddress(&p_dw, g_dw);
    cudaGetSymbolAddress(&p_cnt, g_counts);
    cudaGetSymbolAddress(&p_loss, g_loss);
    cudaMemsetAsync(p_dw, 0, sizeof(float) * DIM * KCODES, 0);
    cudaMemsetAsync(p_cnt, 0, sizeof(float) * KCODES, 0);
    cudaMemsetAsync(p_loss, 0, sizeof(float), 0);

    cudaFuncSetAttribute(vq_hmma, cudaFuncAttributeMaxDynamicSharedMemorySize, SMEM_MAIN);

    prep_x<<<(NROWS * DIM / 4) / 256, 256>>>(x);
    prep_e<<<dim3(KCODES / 32, DIM / 32), 256>>>(emb);
    esq_kernel<<<KCODES / 256, 256>>>(emb);
    vq_hmma<<<NROWS / 128, 256, SMEM_MAIN>>>(x, emb, out);
    finalize_kernel<<<1, 256>>>(ema_cs, counter, out);
    emb_out_kernel<<<(DIM * KCODES) / 256, 256>>>(ema_dw, emb, istrain, out + EMB_OFF);
}